// round 13
// baseline (speedup 1.0000x reference)
#include <cuda_runtime.h>
#include <cuda_fp16.h>
#include <cuda_bf16.h>
#include <cstdint>

#define CC   256
#define MM   2024
#define NPIX 32768
#define CHID 64
#define PT   64
#define KT   32
#define NTILE 64          // tiles per bank
#define NTT  128          // total (fg+bg)
#define INV_TEMP (1.0f/0.03f)

// attn dynamic smem: 3 tile buffers (T1F fp16 16KB + T2F bf16 16KB each)
#define TB_SZ    32768
#define SMEM_DYN (3*TB_SZ)

#define XN_SMEM (64*260*4)

// ---------------- global scratch ----------------
__device__ float g_xn[(size_t)NPIX*CC];
__device__ float g_gfg[NPIX];
__device__ float g_gbg[NPIX];
__device__ __align__(16) uint4 g_qf[(size_t)(NPIX/64)*2048];   // fp16 A-frags, [64px blocks][4mt][16ks][32lane]
__device__ __align__(16) uint2 g_timg[(size_t)NTT*4096];       // 128 tiles * 32KB
__device__ __align__(16) uint2 g_wf[8192];                     // w1 fp16 B-frags (fg+bg)

// ---------------- helpers ----------------
__device__ __forceinline__ uint32_t s2u(const void* p){
    uint32_t a;
    asm("{ .reg .u64 t; cvta.to.shared.u64 t, %1; cvt.u32.u64 %0, t; }" : "=r"(a) : "l"(p));
    return a;
}
__device__ __forceinline__ uint32_t ph2(float x, float y){
    __half2 h = __floats2half2_rn(x, y);
    return *(uint32_t*)&h;
}
__device__ __forceinline__ uint32_t pbf2(float x, float y){
    __nv_bfloat162 h = __floats2bfloat162_rn(x, y);
    return *(uint32_t*)&h;
}
__device__ __forceinline__ void mbar_init(uint32_t m, uint32_t c){
    asm volatile("mbarrier.init.shared.b64 [%0], %1;" :: "r"(m), "r"(c) : "memory");
}
__device__ __forceinline__ void mbar_tx(uint32_t m, uint32_t b){
    asm volatile("mbarrier.arrive.expect_tx.shared.b64 _, [%0], %1;" :: "r"(m), "r"(b) : "memory");
}
__device__ __forceinline__ void mbar_arrive(uint32_t m){
    asm volatile("mbarrier.arrive.shared.b64 _, [%0];" :: "r"(m) : "memory");
}
__device__ __forceinline__ void mbar_wait(uint32_t m, uint32_t ph){
    asm volatile(
        "{\n\t.reg .pred P;\n\t"
        "W_%=:\n\t"
        "mbarrier.try_wait.parity.acquire.cta.shared::cta.b64 P, [%0], %1, 0x989680;\n\t"
        "@P bra D_%=;\n\tbra W_%=;\n\tD_%=:\n\t}"
        :: "r"(m), "r"(ph) : "memory");
}
__device__ __forceinline__ void bulk_g2s(uint32_t dst, const void* src, uint32_t bytes, uint32_t mbar){
    asm volatile("cp.async.bulk.shared::cluster.global.mbarrier::complete_tx::bytes [%0], [%1], %2, [%3];"
        :: "r"(dst), "l"(src), "r"(bytes), "r"(mbar) : "memory");
}
// m16n8k16 fp16 mma, fp32 accum
__device__ __forceinline__ void mma16(float* d, uint4 a, uint2 b){
    asm volatile("mma.sync.aligned.m16n8k16.row.col.f32.f16.f16.f32 "
        "{%0,%1,%2,%3}, {%4,%5,%6,%7}, {%8,%9}, {%0,%1,%2,%3};"
        : "+f"(d[0]), "+f"(d[1]), "+f"(d[2]), "+f"(d[3])
        : "r"(a.x), "r"(a.y), "r"(a.z), "r"(a.w), "r"(b.x), "r"(b.y));
}
// m16n8k16 bf16 mma, fp32 accum
__device__ __forceinline__ void mma16b(float* d, uint4 a, uint2 b){
    asm volatile("mma.sync.aligned.m16n8k16.row.col.f32.bf16.bf16.f32 "
        "{%0,%1,%2,%3}, {%4,%5,%6,%7}, {%8,%9}, {%0,%1,%2,%3};"
        : "+f"(d[0]), "+f"(d[1]), "+f"(d[2]), "+f"(d[3])
        : "r"(a.x), "r"(a.y), "r"(a.z), "r"(a.w), "r"(b.x), "r"(b.y));
}

// ---------------------------------------------------------------------------
// P1: normalize memory rows -> frag-major tile images.
// T1F (GEMM1 B fp16, k=channel, *INV_TEMP): [4nt][16ks][32lane] uint2 (16KB)
// T2F (GEMM2 B bf16, k=slot):               [32nt][2ks][32lane]  uint2 (16KB)
// ---------------------------------------------------------------------------
__global__ void pack_mem_kernel(const float* __restrict__ fg, const float* __restrict__ bg){
    __shared__ float rows[KT][CC+4];
    int blk = blockIdx.x;                 // 0..127
    int bank = blk >> 6, tin = blk & 63;
    const float* src = bank ? bg : fg;
    int tid = threadIdx.x, wid = tid>>5, lane = tid&31;

    #pragma unroll
    for (int i = 0; i < 4; i++){
        int r = wid*4 + i;
        int slot = tin*KT + r;
        float4 v0 = make_float4(0.f,0.f,0.f,0.f), v1 = v0;
        if (slot < MM){
            const float4* s4 = (const float4*)(src + (size_t)slot*CC);
            v0 = s4[lane]; v1 = s4[lane+32];
            float ss = v0.x*v0.x+v0.y*v0.y+v0.z*v0.z+v0.w*v0.w
                     + v1.x*v1.x+v1.y*v1.y+v1.z*v1.z+v1.w*v1.w;
            #pragma unroll
            for (int o = 16; o; o >>= 1) ss += __shfl_xor_sync(0xffffffffu, ss, o);
            float inv = 1.0f / fmaxf(sqrtf(ss), 1e-12f);
            v0.x*=inv; v0.y*=inv; v0.z*=inv; v0.w*=inv;
            v1.x*=inv; v1.y*=inv; v1.z*=inv; v1.w*=inv;
        }
        float4* d = (float4*)&rows[r][0];
        d[lane] = v0; d[lane+32] = v1;
    }
    __syncthreads();

    uint2* out = g_timg + (size_t)blk * 4096;
    for (int idx = tid; idx < 2048; idx += 256){
        int nt = idx>>9, ks = (idx>>5)&15, l = idx&31;
        int g = l>>2, t = l&3;
        int slot = nt*8 + g, c = ks*16 + 2*t;
        uint2 v;
        v.x = ph2(rows[slot][c]   * INV_TEMP, rows[slot][c+1] * INV_TEMP);
        v.y = ph2(rows[slot][c+8] * INV_TEMP, rows[slot][c+9] * INV_TEMP);
        out[idx] = v;
    }
    for (int idx = tid; idx < 2048; idx += 256){
        int nt2 = idx>>6, ks2 = (idx>>5)&1, l = idx&31;
        int g = l>>2, t = l&3;
        int ch = nt2*8 + g, s0 = ks2*16 + 2*t;
        uint2 v;
        v.x = pbf2(rows[s0][ch],   rows[s0+1][ch]);
        v.y = pbf2(rows[s0+8][ch], rows[s0+9][ch]);
        out[2048 + idx] = v;
    }
}

// ---------------------------------------------------------------------------
// P2: pack w1 (fg,bg) fp16 B-frags: [bank][8nt][16ks][32lane] uint2
// ---------------------------------------------------------------------------
__global__ void wpack_kernel(const float* __restrict__ w1f, const float* __restrict__ w1b){
    int idx = blockIdx.x*256 + threadIdx.x;      // 0..8191
    int bank = idx >> 12, r = idx & 4095;
    int nt = r>>9, ks = (r>>5)&15, l = r&31;
    int g = l>>2, t = l&3;
    int hcol = nt*8 + g, c = ks*16 + 2*t;
    const float* w = bank ? w1b : w1f;
    uint2 v;
    v.x = ph2(w[c*CHID + hcol],     w[(c+1)*CHID + hcol]);
    v.y = ph2(w[(c+8)*CHID + hcol], w[(c+9)*CHID + hcol]);
    g_wf[idx] = v;
}

// ---------------------------------------------------------------------------
// P3: feats -> g_xn (fp32) + g_qf (fp16 A-frags). One block per 64 pixels.
// ---------------------------------------------------------------------------
__global__ void xn_kernel(const float* __restrict__ feats){
    extern __shared__ float xr[];               // [64][260]
    __shared__ float part[4][64];
    __shared__ float sinv[64];
    int bh = blockIdx.x, b = bh >> 6, h = bh & 63;
    int tid = threadIdx.x;
    int w = tid & 63, cg = tid >> 6;
    float ps = 0.f;
    for (int c = cg; c < CC; c += 4){
        float v = feats[(((size_t)b*CC + c)*64 + h)*64 + w];
        ps = fmaf(v, v, ps);
    }
    part[cg][w] = ps;
    __syncthreads();
    if (tid < 64){
        float s = part[0][tid] + part[1][tid] + part[2][tid] + part[3][tid];
        sinv[tid] = 1.0f / fmaxf(sqrtf(s), 1e-12f);
    }
    __syncthreads();
    int nbase = bh * 64;
    for (int i = tid; i < CC*64; i += 256){
        int ww = i >> 8, c = i & 255;
        float v = feats[(((size_t)b*CC + c)*64 + h)*64 + ww] * sinv[ww];
        g_xn[(size_t)(nbase + ww)*CC + c] = v;
        xr[ww*260 + c] = v;
    }
    __syncthreads();
    uint4* out = g_qf + (size_t)bh * 2048;
    for (int idx = tid; idx < 2048; idx += 256){
        int mt = idx>>9, ks = (idx>>5)&15, l = idx&31;
        int g = l>>2, t = l&3;
        int m = mt*16 + g, k = ks*16 + 2*t;
        uint4 v;
        v.x = ph2(xr[m*260 + k],       xr[m*260 + k+1]);
        v.y = ph2(xr[(m+8)*260 + k],   xr[(m+8)*260 + k+1]);
        v.z = ph2(xr[m*260 + k+8],     xr[m*260 + k+9]);
        v.w = ph2(xr[(m+8)*260 + k+8], xr[(m+8)*260 + k+9]);
        out[idx] = v;
    }
}

// ---------------------------------------------------------------------------
// P4: gate MLPs via fp16 mma. CTA = 64 px; warp: mt=w&3, bank=w>>2.
// ---------------------------------------------------------------------------
__global__ __launch_bounds__(256) void gate_kernel(
    const float* __restrict__ b1f, const float* __restrict__ w2f, const float* __restrict__ b2f,
    const float* __restrict__ b1b, const float* __restrict__ w2b, const float* __restrict__ b2b){
    int cta = blockIdx.x, tid = threadIdx.x, wid = tid>>5, lane = tid&31;
    int mt = wid & 3, bank = wid >> 2;
    const uint4* A = g_qf + (size_t)cta*2048 + mt*512 + lane;
    const uint2* B = g_wf + bank*4096 + lane;

    float acc[8][4];
    #pragma unroll
    for (int nt = 0; nt < 8; nt++)
        acc[nt][0] = acc[nt][1] = acc[nt][2] = acc[nt][3] = 0.f;

    #pragma unroll 4
    for (int ks = 0; ks < 16; ks++){
        uint4 a = A[ks*32];
        #pragma unroll
        for (int nt = 0; nt < 8; nt++)
            mma16(acc[nt], a, B[(nt*16 + ks)*32]);
    }

    const float* b1 = bank ? b1b : b1f;
    const float* w2 = bank ? w2b : w2f;
    float bias2 = bank ? b2b[0] : b2f[0];
    float sA = 0.f, sB = 0.f;
    #pragma unroll
    for (int nt = 0; nt < 8; nt++){
        #pragma unroll
        for (int c = 0; c < 4; c++){
            int col = nt*8 + 2*(lane&3) + (c&1);
            float hv = fmaxf(acc[nt][c] + b1[col], 0.f) * w2[col];
            if (c < 2) sA += hv; else sB += hv;
        }
    }
    sA += __shfl_xor_sync(0xffffffffu, sA, 1);
    sA += __shfl_xor_sync(0xffffffffu, sA, 2);
    sB += __shfl_xor_sync(0xffffffffu, sB, 1);
    sB += __shfl_xor_sync(0xffffffffu, sB, 2);
    if ((lane & 3) == 0){
        int rA = cta*64 + mt*16 + (lane>>2);
        float* dst = bank ? g_gbg : g_gfg;
        dst[rA]     = 1.0f / (1.0f + __expf(-(sA + bias2)));
        dst[rA + 8] = 1.0f / (1.0f + __expf(-(sB + bias2)));
    }
}

// ---------------------------------------------------------------------------
// P5: fused dual attention. CTA = 64 pixels, 4 warps, occupancy 2.
// Q held in registers (no smem A traffic). 3-deep tile ring with full/empty
// mbarriers: NO __syncthreads in the main loop — warps free-run.
// GEMM1: 1mt x 4nt x 16ks (fp16); P register-forwarded; GEMM2: 1mt x 32nt x 2ks (bf16).
// ---------------------------------------------------------------------------
__global__ __launch_bounds__(128, 2) void attn_kernel(float* __restrict__ out){
    extern __shared__ __align__(16) char sm[];
    __shared__ __align__(8) unsigned long long barsm[6];   // full[3], empty[3]

    const int tid = threadIdx.x, wid = tid >> 5, lane = tid & 31;
    const int g = lane >> 2, t = lane & 3;
    const int cta = blockIdx.x;

    const uint32_t smb = s2u(sm);
    const uint32_t barb = s2u(barsm);
    // full[i] = barb + 8*i ; empty[i] = barb + 24 + 8*i

    if (tid == 0){
        #pragma unroll
        for (int i = 0; i < 3; i++){
            mbar_init(barb + 8*i, 1);        // full: tx-based
            mbar_init(barb + 24 + 8*i, 4);   // empty: one arrive per warp
        }
    }
    __syncthreads();

    // ---- Q A-frags into registers (16 uint4 per thread, once) ----
    uint4 Qreg[16];
    {
        const uint4* Ag = g_qf + (size_t)cta*2048 + wid*512 + lane;
        #pragma unroll
        for (int ks = 0; ks < 16; ks++) Qreg[ks] = Ag[ks*32];
    }

    if (tid == 0){
        #pragma unroll
        for (int i = 0; i < 2; i++){
            mbar_tx(barb + 8*i, TB_SZ);
            bulk_g2s(smb + i*TB_SZ, g_timg + (size_t)i*4096, TB_SZ, barb + 8*i);
        }
    }

    const int rA = cta*64 + wid*16 + g;      // this thread's row A
    const int rB = rA + 8;                   // row B

    for (int pass = 0; pass < 2; pass++){
        float accO[32][4];
        #pragma unroll
        for (int j = 0; j < 32; j++)
            accO[j][0] = accO[j][1] = accO[j][2] = accO[j][3] = 0.f;
        float lA = 0.f, lB = 0.f;

        for (int tt = 0; tt < NTILE; tt++){
            const int tgl = pass*NTILE + tt;
            const int buf = tgl % 3;
            char* TB = sm + buf*TB_SZ;

            // ---- producer: prefetch tile tgl+2 (waits on empties with 1-tile slack) ----
            if (tid == 0 && tgl + 2 < NTT){
                const int pt = tgl + 2;
                const int pb = pt % 3;
                if (pt >= 3) mbar_wait(barb + 24 + 8*pb, ((pt - 3)/3) & 1);
                mbar_tx(barb + 8*pb, TB_SZ);
                bulk_g2s(smb + pb*TB_SZ, g_timg + (size_t)pt*4096, TB_SZ, barb + 8*pb);
            }

            // ---- consumer: wait tile data ----
            mbar_wait(barb + 8*buf, (tgl/3) & 1);

            // ---- GEMM1: 1mt x 4nt x 16ks (fp16), A in registers ----
            float accS[4][4];
            #pragma unroll
            for (int j = 0; j < 4; j++)
                accS[j][0] = accS[j][1] = accS[j][2] = accS[j][3] = 0.f;
            {
                const uint2* Bq = (const uint2*)TB + lane;
                #pragma unroll 4
                for (int ks = 0; ks < 16; ks++){
                    uint4 a = Qreg[ks];
                    mma16(accS[0], a, Bq[(ks      )*32]);
                    mma16(accS[1], a, Bq[(ks + 16 )*32]);
                    mma16(accS[2], a, Bq[(ks + 32 )*32]);
                    mma16(accS[3], a, Bq[(ks + 48 )*32]);
                }
            }

            // ---- exp + pack P directly into GEMM2 A-frags (registers) ----
            uint4 aP[2];
            {
                const bool last = (tt == NTILE-1);
                #pragma unroll
                for (int ks2 = 0; ks2 < 2; ks2++){
                    #pragma unroll
                    for (int h = 0; h < 2; h++){
                        const int nt = 2*ks2 + h;
                        float p0 = __expf(accS[nt][0]);
                        float p1 = __expf(accS[nt][1]);
                        float p2 = __expf(accS[nt][2]);
                        float p3 = __expf(accS[nt][3]);
                        if (last && nt > 0){ p0 = p1 = p2 = p3 = 0.f; }
                        uint32_t uA = pbf2(p0, p1);
                        uint32_t uB = pbf2(p2, p3);
                        if (h == 0){ aP[ks2].x = uA; aP[ks2].y = uB; }
                        else        { aP[ks2].z = uA; aP[ks2].w = uB; }
                        lA += __uint_as_float(uA << 16) + __uint_as_float(uA & 0xFFFF0000u);
                        lB += __uint_as_float(uB << 16) + __uint_as_float(uB & 0xFFFF0000u);
                    }
                }
            }

            // ---- GEMM2: 1mt x 32nt x 2ks (bf16), A in registers ----
            {
                const uint2* B2 = (const uint2*)(TB + 16384) + lane;
                #pragma unroll
                for (int ks2 = 0; ks2 < 2; ks2++){
                    uint4 a = aP[ks2];
                    #pragma unroll
                    for (int j = 0; j < 32; j++)
                        mma16b(accO[j], a, B2[(j*2 + ks2)*32]);
                }
            }

            // ---- this warp is done with buffer ----
            __syncwarp();
            if (lane == 0) mbar_arrive(barb + 24 + 8*buf);
        }

        // ---- row sums: quad-reduce over t ----
        lA += __shfl_xor_sync(0xffffffffu, lA, 1);
        lA += __shfl_xor_sync(0xffffffffu, lA, 2);
        lB += __shfl_xor_sync(0xffffffffu, lB, 1);
        lB += __shfl_xor_sync(0xffffffffu, lB, 2);

        // ---- output epilogue (per-warp independent; no sync) ----
        {
            const float gA = pass ? g_gbg[rA] : g_gfg[rA];
            const float gB = pass ? g_gbg[rB] : g_gfg[rB];
            const float cA = gA / lA;
            const float cB = gB / lB;
            const size_t baseA = ((size_t)(rA >> 12) * CC) * 4096 + (rA & 4095);
            const size_t baseB = baseA + 8;
            const float* xnA = g_xn + (size_t)rA*CC;
            const float* xnB = g_xn + (size_t)rB*CC;
            #pragma unroll
            for (int j = 0; j < 32; j++){
                int c0 = j*8 + 2*t;
                size_t aA = baseA + (size_t)c0*4096;
                size_t aB = baseB + (size_t)c0*4096;
                if (pass == 0){
                    out[aA]        = xnA[c0]   + cA*accO[j][0];
                    out[aA + 4096] = xnA[c0+1] + cA*accO[j][1];
                    out[aB]        = xnB[c0]   + cB*accO[j][2];
                    out[aB + 4096] = xnB[c0+1] + cB*accO[j][3];
                } else {
                    out[aA]        -= cA*accO[j][0];
                    out[aA + 4096] -= cA*accO[j][1];
                    out[aB]        -= cB*accO[j][2];
                    out[aB + 4096] -= cB*accO[j][3];
                }
            }
        }
    }
}

// ---------------------------------------------------------------------------
extern "C" void kernel_launch(void* const* d_in, const int* in_sizes, int n_in,
                              void* d_out, int out_size){
    const float* feats = (const float*)d_in[0];
    const float* fgm   = (const float*)d_in[1];
    const float* bgm   = (const float*)d_in[2];
    const float* w1f   = (const float*)d_in[3];
    const float* b1f   = (const float*)d_in[4];
    const float* w2f   = (const float*)d_in[5];
    const float* b2f   = (const float*)d_in[6];
    const float* w1b   = (const float*)d_in[7];
    const float* b1b   = (const float*)d_in[8];
    const float* w2b   = (const float*)d_in[9];
    const float* b2b   = (const float*)d_in[10];
    float* out = (float*)d_out;

    cudaFuncSetAttribute(attn_kernel, cudaFuncAttributeMaxDynamicSharedMemorySize, SMEM_DYN);
    cudaFuncSetAttribute(xn_kernel, cudaFuncAttributeMaxDynamicSharedMemorySize, XN_SMEM);

    pack_mem_kernel<<<128, 256>>>(fgm, bgm);
    wpack_kernel<<<32, 256>>>(w1f, w1b);
    xn_kernel<<<512, 256, XN_SMEM>>>(feats);
    gate_kernel<<<512, 256>>>(b1f, w2f, b2f, b1b, w2b, b2b);
    attn_kernel<<<NPIX / PT, 128, SMEM_DYN>>>(out);
}

// round 14
// speedup vs baseline: 1.2587x; 1.2587x over previous
#include <cuda_runtime.h>
#include <cuda_fp16.h>
#include <cuda_bf16.h>
#include <cstdint>

#define CC   256
#define MM   2024
#define NPIX 32768
#define CHID 64
#define PT   64
#define KT   32
#define NTILE 64          // tiles per bank
#define NTT  128          // total (fg+bg)
#define INV_TEMP (1.0f/0.03f)

// attn dynamic smem: QF 32KB + 2 tile buffers (T1F fp16 16KB + T2F bf16 16KB)
#define QF_OFF   0
#define TB_OFF   32768
#define TB_SZ    32768
#define SMEM_DYN 98304

#define XN_SMEM (64*260*4)

// ---------------- global scratch ----------------
__device__ float g_xn[(size_t)NPIX*CC];
__device__ float g_gfg[NPIX];
__device__ float g_gbg[NPIX];
__device__ __align__(16) uint4 g_qf[(size_t)(NPIX/64)*2048];   // fp16 A-frags, [64px blocks][4mt][16ks][32lane]
__device__ __align__(16) uint2 g_timg[(size_t)NTT*4096];       // 128 tiles * 32KB
__device__ __align__(16) uint2 g_wf[8192];                     // w1 fp16 B-frags (fg+bg)

// ---------------- helpers ----------------
__device__ __forceinline__ uint32_t s2u(const void* p){
    uint32_t a;
    asm("{ .reg .u64 t; cvta.to.shared.u64 t, %1; cvt.u32.u64 %0, t; }" : "=r"(a) : "l"(p));
    return a;
}
__device__ __forceinline__ uint32_t ph2(float x, float y){
    __half2 h = __floats2half2_rn(x, y);
    return *(uint32_t*)&h;
}
__device__ __forceinline__ uint32_t pbf2(float x, float y){
    __nv_bfloat162 h = __floats2bfloat162_rn(x, y);
    return *(uint32_t*)&h;
}
__device__ __forceinline__ void mbar_init(uint32_t m, uint32_t c){
    asm volatile("mbarrier.init.shared.b64 [%0], %1;" :: "r"(m), "r"(c) : "memory");
}
__device__ __forceinline__ void mbar_tx(uint32_t m, uint32_t b){
    asm volatile("mbarrier.arrive.expect_tx.shared.b64 _, [%0], %1;" :: "r"(m), "r"(b) : "memory");
}
__device__ __forceinline__ void mbar_wait(uint32_t m, uint32_t ph){
    asm volatile(
        "{\n\t.reg .pred P;\n\t"
        "W_%=:\n\t"
        "mbarrier.try_wait.parity.acquire.cta.shared::cta.b64 P, [%0], %1, 0x989680;\n\t"
        "@P bra D_%=;\n\tbra W_%=;\n\tD_%=:\n\t}"
        :: "r"(m), "r"(ph) : "memory");
}
__device__ __forceinline__ void bulk_g2s(uint32_t dst, const void* src, uint32_t bytes, uint32_t mbar){
    asm volatile("cp.async.bulk.shared::cluster.global.mbarrier::complete_tx::bytes [%0], [%1], %2, [%3];"
        :: "r"(dst), "l"(src), "r"(bytes), "r"(mbar) : "memory");
}
// m16n8k16 fp16 mma, fp32 accum
__device__ __forceinline__ void mma16(float* d, uint4 a, uint2 b){
    asm volatile("mma.sync.aligned.m16n8k16.row.col.f32.f16.f16.f32 "
        "{%0,%1,%2,%3}, {%4,%5,%6,%7}, {%8,%9}, {%0,%1,%2,%3};"
        : "+f"(d[0]), "+f"(d[1]), "+f"(d[2]), "+f"(d[3])
        : "r"(a.x), "r"(a.y), "r"(a.z), "r"(a.w), "r"(b.x), "r"(b.y));
}
// m16n8k16 bf16 mma, fp32 accum
__device__ __forceinline__ void mma16b(float* d, uint4 a, uint2 b){
    asm volatile("mma.sync.aligned.m16n8k16.row.col.f32.bf16.bf16.f32 "
        "{%0,%1,%2,%3}, {%4,%5,%6,%7}, {%8,%9}, {%0,%1,%2,%3};"
        : "+f"(d[0]), "+f"(d[1]), "+f"(d[2]), "+f"(d[3])
        : "r"(a.x), "r"(a.y), "r"(a.z), "r"(a.w), "r"(b.x), "r"(b.y));
}

// ---------------------------------------------------------------------------
// P1: normalize memory rows -> frag-major tile images.
// T1F (GEMM1 B fp16, k=channel, *INV_TEMP): [4nt][16ks][32lane] uint2 (16KB)
// T2F (GEMM2 B bf16, k=slot):               [32nt][2ks][32lane]  uint2 (16KB)
// ---------------------------------------------------------------------------
__global__ void pack_mem_kernel(const float* __restrict__ fg, const float* __restrict__ bg){
    __shared__ float rows[KT][CC+4];
    int blk = blockIdx.x;                 // 0..127
    int bank = blk >> 6, tin = blk & 63;
    const float* src = bank ? bg : fg;
    int tid = threadIdx.x, wid = tid>>5, lane = tid&31;

    #pragma unroll
    for (int i = 0; i < 4; i++){
        int r = wid*4 + i;
        int slot = tin*KT + r;
        float4 v0 = make_float4(0.f,0.f,0.f,0.f), v1 = v0;
        if (slot < MM){
            const float4* s4 = (const float4*)(src + (size_t)slot*CC);
            v0 = s4[lane]; v1 = s4[lane+32];
            float ss = v0.x*v0.x+v0.y*v0.y+v0.z*v0.z+v0.w*v0.w
                     + v1.x*v1.x+v1.y*v1.y+v1.z*v1.z+v1.w*v1.w;
            #pragma unroll
            for (int o = 16; o; o >>= 1) ss += __shfl_xor_sync(0xffffffffu, ss, o);
            float inv = 1.0f / fmaxf(sqrtf(ss), 1e-12f);
            v0.x*=inv; v0.y*=inv; v0.z*=inv; v0.w*=inv;
            v1.x*=inv; v1.y*=inv; v1.z*=inv; v1.w*=inv;
        }
        float4* d = (float4*)&rows[r][0];
        d[lane] = v0; d[lane+32] = v1;
    }
    __syncthreads();

    uint2* out = g_timg + (size_t)blk * 4096;
    for (int idx = tid; idx < 2048; idx += 256){
        int nt = idx>>9, ks = (idx>>5)&15, l = idx&31;
        int g = l>>2, t = l&3;
        int slot = nt*8 + g, c = ks*16 + 2*t;
        uint2 v;
        v.x = ph2(rows[slot][c]   * INV_TEMP, rows[slot][c+1] * INV_TEMP);
        v.y = ph2(rows[slot][c+8] * INV_TEMP, rows[slot][c+9] * INV_TEMP);
        out[idx] = v;
    }
    for (int idx = tid; idx < 2048; idx += 256){
        int nt2 = idx>>6, ks2 = (idx>>5)&1, l = idx&31;
        int g = l>>2, t = l&3;
        int ch = nt2*8 + g, s0 = ks2*16 + 2*t;
        uint2 v;
        v.x = pbf2(rows[s0][ch],   rows[s0+1][ch]);
        v.y = pbf2(rows[s0+8][ch], rows[s0+9][ch]);
        out[2048 + idx] = v;
    }
}

// ---------------------------------------------------------------------------
// P2: pack w1 (fg,bg) fp16 B-frags: [bank][8nt][16ks][32lane] uint2
// ---------------------------------------------------------------------------
__global__ void wpack_kernel(const float* __restrict__ w1f, const float* __restrict__ w1b){
    int idx = blockIdx.x*256 + threadIdx.x;      // 0..8191
    int bank = idx >> 12, r = idx & 4095;
    int nt = r>>9, ks = (r>>5)&15, l = r&31;
    int g = l>>2, t = l&3;
    int hcol = nt*8 + g, c = ks*16 + 2*t;
    const float* w = bank ? w1b : w1f;
    uint2 v;
    v.x = ph2(w[c*CHID + hcol],     w[(c+1)*CHID + hcol]);
    v.y = ph2(w[(c+8)*CHID + hcol], w[(c+9)*CHID + hcol]);
    g_wf[idx] = v;
}

// ---------------------------------------------------------------------------
// P3: feats -> g_xn (fp32) + g_qf (fp16 A-frags). One block per 64 pixels.
// ---------------------------------------------------------------------------
__global__ void xn_kernel(const float* __restrict__ feats){
    extern __shared__ float xr[];               // [64][260]
    __shared__ float part[4][64];
    __shared__ float sinv[64];
    int bh = blockIdx.x, b = bh >> 6, h = bh & 63;
    int tid = threadIdx.x;
    int w = tid & 63, cg = tid >> 6;
    float ps = 0.f;
    for (int c = cg; c < CC; c += 4){
        float v = feats[(((size_t)b*CC + c)*64 + h)*64 + w];
        ps = fmaf(v, v, ps);
    }
    part[cg][w] = ps;
    __syncthreads();
    if (tid < 64){
        float s = part[0][tid] + part[1][tid] + part[2][tid] + part[3][tid];
        sinv[tid] = 1.0f / fmaxf(sqrtf(s), 1e-12f);
    }
    __syncthreads();
    int nbase = bh * 64;
    for (int i = tid; i < CC*64; i += 256){
        int ww = i >> 8, c = i & 255;
        float v = feats[(((size_t)b*CC + c)*64 + h)*64 + ww] * sinv[ww];
        g_xn[(size_t)(nbase + ww)*CC + c] = v;
        xr[ww*260 + c] = v;
    }
    __syncthreads();
    uint4* out = g_qf + (size_t)bh * 2048;
    for (int idx = tid; idx < 2048; idx += 256){
        int mt = idx>>9, ks = (idx>>5)&15, l = idx&31;
        int g = l>>2, t = l&3;
        int m = mt*16 + g, k = ks*16 + 2*t;
        uint4 v;
        v.x = ph2(xr[m*260 + k],       xr[m*260 + k+1]);
        v.y = ph2(xr[(m+8)*260 + k],   xr[(m+8)*260 + k+1]);
        v.z = ph2(xr[m*260 + k+8],     xr[m*260 + k+9]);
        v.w = ph2(xr[(m+8)*260 + k+8], xr[(m+8)*260 + k+9]);
        out[idx] = v;
    }
}

// ---------------------------------------------------------------------------
// P4: gate MLPs via fp16 mma. CTA = 64 px; warp: mt=w&3, bank=w>>2.
// ---------------------------------------------------------------------------
__global__ __launch_bounds__(256) void gate_kernel(
    const float* __restrict__ b1f, const float* __restrict__ w2f, const float* __restrict__ b2f,
    const float* __restrict__ b1b, const float* __restrict__ w2b, const float* __restrict__ b2b){
    int cta = blockIdx.x, tid = threadIdx.x, wid = tid>>5, lane = tid&31;
    int mt = wid & 3, bank = wid >> 2;
    const uint4* A = g_qf + (size_t)cta*2048 + mt*512 + lane;
    const uint2* B = g_wf + bank*4096 + lane;

    float acc[8][4];
    #pragma unroll
    for (int nt = 0; nt < 8; nt++)
        acc[nt][0] = acc[nt][1] = acc[nt][2] = acc[nt][3] = 0.f;

    #pragma unroll 4
    for (int ks = 0; ks < 16; ks++){
        uint4 a = A[ks*32];
        #pragma unroll
        for (int nt = 0; nt < 8; nt++)
            mma16(acc[nt], a, B[(nt*16 + ks)*32]);
    }

    const float* b1 = bank ? b1b : b1f;
    const float* w2 = bank ? w2b : w2f;
    float bias2 = bank ? b2b[0] : b2f[0];
    float sA = 0.f, sB = 0.f;
    #pragma unroll
    for (int nt = 0; nt < 8; nt++){
        #pragma unroll
        for (int c = 0; c < 4; c++){
            int col = nt*8 + 2*(lane&3) + (c&1);
            float hv = fmaxf(acc[nt][c] + b1[col], 0.f) * w2[col];
            if (c < 2) sA += hv; else sB += hv;
        }
    }
    sA += __shfl_xor_sync(0xffffffffu, sA, 1);
    sA += __shfl_xor_sync(0xffffffffu, sA, 2);
    sB += __shfl_xor_sync(0xffffffffu, sB, 1);
    sB += __shfl_xor_sync(0xffffffffu, sB, 2);
    if ((lane & 3) == 0){
        int rA = cta*64 + mt*16 + (lane>>2);
        float* dst = bank ? g_gbg : g_gfg;
        dst[rA]     = 1.0f / (1.0f + __expf(-(sA + bias2)));
        dst[rA + 8] = 1.0f / (1.0f + __expf(-(sB + bias2)));
    }
}

// ---------------------------------------------------------------------------
// P5: fused dual attention. CTA = 64 pixels, 4 warps, occupancy 2.
// GEMM1: 1mt x 4nt x 16ks (fp16). P forwarded in registers (S D-frag == A-frag).
// GEMM2: 1mt x 32nt x 2ks (bf16), no smem P, no softmax stats, 1 sync/tile.
// ---------------------------------------------------------------------------
__global__ __launch_bounds__(128, 2) void attn_kernel(float* __restrict__ out){
    extern __shared__ __align__(16) char sm[];
    __shared__ __align__(8) unsigned long long barsm[3];

    const int tid = threadIdx.x, wid = tid >> 5, lane = tid & 31;
    const int g = lane >> 2, t = lane & 3;
    const int cta = blockIdx.x;

    const uint32_t smb = s2u(sm);
    const uint4* QF4 = (const uint4*)(sm + QF_OFF);
    const uint32_t qbar = s2u(barsm);
    const uint32_t fbar0 = qbar + 8, fbar1 = qbar + 16;

    if (tid == 0){ mbar_init(qbar,1); mbar_init(fbar0,1); mbar_init(fbar1,1); }
    __syncthreads();
    if (tid == 0){
        mbar_tx(qbar, 32768);
        bulk_g2s(smb + QF_OFF, g_qf + (size_t)cta*2048, 32768, qbar);
        mbar_tx(fbar0, TB_SZ);
        bulk_g2s(smb + TB_OFF, g_timg, TB_SZ, fbar0);
        mbar_tx(fbar1, TB_SZ);
        bulk_g2s(smb + TB_OFF + TB_SZ, g_timg + 4096, TB_SZ, fbar1);
    }
    mbar_wait(qbar, 0);

    const int rA = cta*64 + wid*16 + g;      // this thread's row A
    const int rB = rA + 8;                   // row B

    for (int pass = 0; pass < 2; pass++){
        float accO[32][4];
        #pragma unroll
        for (int j = 0; j < 32; j++)
            accO[j][0] = accO[j][1] = accO[j][2] = accO[j][3] = 0.f;
        float lA = 0.f, lB = 0.f;
        const float gA = pass ? g_gbg[rA] : g_gfg[rA];   // hoisted off epilogue path
        const float gB = pass ? g_gbg[rB] : g_gfg[rB];

        for (int tt = 0; tt < NTILE; tt++){
            const int tgl = pass*NTILE + tt;
            const int buf = tgl & 1;
            char* TB = sm + TB_OFF + buf*TB_SZ;
            mbar_wait(buf ? fbar1 : fbar0, (tgl >> 1) & 1);

            // ---- GEMM1: 1mt x 4nt x 16ks (fp16) ----
            float accS[4][4];
            #pragma unroll
            for (int j = 0; j < 4; j++)
                accS[j][0] = accS[j][1] = accS[j][2] = accS[j][3] = 0.f;
            {
                const uint4* Aq = QF4 + wid*512 + lane;
                const uint2* Bq = (const uint2*)TB + lane;
                #pragma unroll
                for (int ks = 0; ks < 16; ks++){
                    uint4 a = Aq[ks*32];
                    mma16(accS[0], a, Bq[(ks      )*32]);
                    mma16(accS[1], a, Bq[(ks + 16 )*32]);
                    mma16(accS[2], a, Bq[(ks + 32 )*32]);
                    mma16(accS[3], a, Bq[(ks + 48 )*32]);
                }
            }

            // ---- exp + pack P into GEMM2 A-frags (registers); fp32 lsum ----
            uint4 aP[2];
            {
                const bool last = (tt == NTILE-1);
                #pragma unroll
                for (int ks2 = 0; ks2 < 2; ks2++){
                    #pragma unroll
                    for (int h = 0; h < 2; h++){
                        const int nt = 2*ks2 + h;
                        float p0 = __expf(accS[nt][0]);
                        float p1 = __expf(accS[nt][1]);
                        float p2 = __expf(accS[nt][2]);
                        float p3 = __expf(accS[nt][3]);
                        if (last && nt > 0){ p0 = p1 = p2 = p3 = 0.f; }
                        lA += p0 + p1;
                        lB += p2 + p3;
                        uint32_t uA = pbf2(p0, p1);
                        uint32_t uB = pbf2(p2, p3);
                        if (h == 0){ aP[ks2].x = uA; aP[ks2].y = uB; }
                        else        { aP[ks2].z = uA; aP[ks2].w = uB; }
                    }
                }
            }

            // ---- GEMM2: 1mt x 32nt x 2ks (bf16), A in registers ----
            {
                const uint2* B2 = (const uint2*)(TB + 16384) + lane;
                #pragma unroll
                for (int ks2 = 0; ks2 < 2; ks2++){
                    uint4 a = aP[ks2];
                    #pragma unroll
                    for (int j = 0; j < 32; j++)
                        mma16b(accO[j], a, B2[(j*2 + ks2)*32]);
                }
            }
            __syncthreads();

            if (tid == 0 && tgl + 2 < NTT){
                uint32_t fb = buf ? fbar1 : fbar0;
                mbar_tx(fb, TB_SZ);
                bulk_g2s(smb + TB_OFF + buf*TB_SZ, g_timg + (size_t)(tgl+2)*4096, TB_SZ, fb);
            }
        }

        // ---- row sums: quad-reduce over t ----
        lA += __shfl_xor_sync(0xffffffffu, lA, 1);
        lA += __shfl_xor_sync(0xffffffffu, lA, 2);
        lB += __shfl_xor_sync(0xffffffffu, lB, 1);
        lB += __shfl_xor_sync(0xffffffffu, lB, 2);

        // ---- output epilogue ----
        {
            const float cA = gA / lA;
            const float cB = gB / lB;
            const size_t baseA = ((size_t)(rA >> 12) * CC) * 4096 + (rA & 4095);
            const size_t baseB = baseA + 8;
            const float* xnA = g_xn + (size_t)rA*CC;
            const float* xnB = g_xn + (size_t)rB*CC;
            #pragma unroll
            for (int j = 0; j < 32; j++){
                int c0 = j*8 + 2*t;
                size_t aA = baseA + (size_t)c0*4096;
                size_t aB = baseB + (size_t)c0*4096;
                if (pass == 0){
                    out[aA]        = xnA[c0]   + cA*accO[j][0];
                    out[aA + 4096] = xnA[c0+1] + cA*accO[j][1];
                    out[aB]        = xnB[c0]   + cB*accO[j][2];
                    out[aB + 4096] = xnB[c0+1] + cB*accO[j][3];
                } else {
                    out[aA]        -= cA*accO[j][0];
                    out[aA + 4096] -= cA*accO[j][1];
                    out[aB]        -= cB*accO[j][2];
                    out[aB + 4096] -= cB*accO[j][3];
                }
            }
        }
    }
}

// ---------------------------------------------------------------------------
extern "C" void kernel_launch(void* const* d_in, const int* in_sizes, int n_in,
                              void* d_out, int out_size){
    const float* feats = (const float*)d_in[0];
    const float* fgm   = (const float*)d_in[1];
    const float* bgm   = (const float*)d_in[2];
    const float* w1f   = (const float*)d_in[3];
    const float* b1f   = (const float*)d_in[4];
    const float* w2f   = (const float*)d_in[5];
    const float* b2f   = (const float*)d_in[6];
    const float* w1b   = (const float*)d_in[7];
    const float* b1b   = (const float*)d_in[8];
    const float* w2b   = (const float*)d_in[9];
    const float* b2b   = (const float*)d_in[10];
    float* out = (float*)d_out;

    cudaFuncSetAttribute(attn_kernel, cudaFuncAttributeMaxDynamicSharedMemorySize, SMEM_DYN);
    cudaFuncSetAttribute(xn_kernel, cudaFuncAttributeMaxDynamicSharedMemorySize, XN_SMEM);

    pack_mem_kernel<<<128, 256>>>(fgm, bgm);
    wpack_kernel<<<32, 256>>>(w1f, w1b);
    xn_kernel<<<512, 256, XN_SMEM>>>(feats);
    gate_kernel<<<512, 256>>>(b1f, w2f, b2f, b1b, w2b, b2b);
    attn_kernel<<<NPIX / PT, 128, SMEM_DYN>>>(out);
}

// round 15
// speedup vs baseline: 1.2788x; 1.0160x over previous
#include <cuda_runtime.h>
#include <cuda_fp16.h>
#include <cuda_bf16.h>
#include <cstdint>

#define CC   256
#define MM   2024
#define NPIX 32768
#define CHID 64
#define PT   64
#define KT   32
#define NTILE 64          // tiles per bank
#define NTT  128          // total (fg+bg)
#define INV_TEMP (1.0f/0.03f)

// attn dynamic smem: QF 32KB + 2 tile buffers (T1F fp16 16KB + T2F bf16 16KB)
#define QF_OFF   0
#define TB_OFF   32768
#define TB_SZ    32768
#define SMEM_DYN 98304

#define XN_SMEM (64*260*4)

// ---------------- global scratch ----------------
__device__ float g_xn[(size_t)NPIX*CC];
__device__ float g_gfg[NPIX];
__device__ float g_gbg[NPIX];
__device__ __align__(16) uint4 g_qf[(size_t)(NPIX/64)*2048];   // fp16 A-frags, [64px blocks][4mt][16ks][32lane]
__device__ __align__(16) uint2 g_timg[(size_t)NTT*4096];       // 128 tiles * 32KB
__device__ __align__(16) uint2 g_wf[8192];                     // w1 fp16 B-frags (fg+bg)

// ---------------- helpers ----------------
__device__ __forceinline__ uint32_t s2u(const void* p){
    uint32_t a;
    asm("{ .reg .u64 t; cvta.to.shared.u64 t, %1; cvt.u32.u64 %0, t; }" : "=r"(a) : "l"(p));
    return a;
}
__device__ __forceinline__ uint32_t ph2(float x, float y){
    __half2 h = __floats2half2_rn(x, y);
    return *(uint32_t*)&h;
}
__device__ __forceinline__ uint32_t pbf2(float x, float y){
    __nv_bfloat162 h = __floats2bfloat162_rn(x, y);
    return *(uint32_t*)&h;
}
__device__ __forceinline__ void mbar_init(uint32_t m, uint32_t c){
    asm volatile("mbarrier.init.shared.b64 [%0], %1;" :: "r"(m), "r"(c) : "memory");
}
__device__ __forceinline__ void mbar_tx(uint32_t m, uint32_t b){
    asm volatile("mbarrier.arrive.expect_tx.shared.b64 _, [%0], %1;" :: "r"(m), "r"(b) : "memory");
}
__device__ __forceinline__ void mbar_arrive(uint32_t m){
    asm volatile("mbarrier.arrive.shared.b64 _, [%0];" :: "r"(m) : "memory");
}
__device__ __forceinline__ void mbar_wait(uint32_t m, uint32_t ph){
    asm volatile(
        "{\n\t.reg .pred P;\n\t"
        "W_%=:\n\t"
        "mbarrier.try_wait.parity.acquire.cta.shared::cta.b64 P, [%0], %1, 0x989680;\n\t"
        "@P bra D_%=;\n\tbra W_%=;\n\tD_%=:\n\t}"
        :: "r"(m), "r"(ph) : "memory");
}
__device__ __forceinline__ void bulk_g2s(uint32_t dst, const void* src, uint32_t bytes, uint32_t mbar){
    asm volatile("cp.async.bulk.shared::cluster.global.mbarrier::complete_tx::bytes [%0], [%1], %2, [%3];"
        :: "r"(dst), "l"(src), "r"(bytes), "r"(mbar) : "memory");
}
// m16n8k16 fp16 mma, fp32 accum
__device__ __forceinline__ void mma16(float* d, uint4 a, uint2 b){
    asm volatile("mma.sync.aligned.m16n8k16.row.col.f32.f16.f16.f32 "
        "{%0,%1,%2,%3}, {%4,%5,%6,%7}, {%8,%9}, {%0,%1,%2,%3};"
        : "+f"(d[0]), "+f"(d[1]), "+f"(d[2]), "+f"(d[3])
        : "r"(a.x), "r"(a.y), "r"(a.z), "r"(a.w), "r"(b.x), "r"(b.y));
}
// m16n8k16 bf16 mma, fp32 accum
__device__ __forceinline__ void mma16b(float* d, uint4 a, uint2 b){
    asm volatile("mma.sync.aligned.m16n8k16.row.col.f32.bf16.bf16.f32 "
        "{%0,%1,%2,%3}, {%4,%5,%6,%7}, {%8,%9}, {%0,%1,%2,%3};"
        : "+f"(d[0]), "+f"(d[1]), "+f"(d[2]), "+f"(d[3])
        : "r"(a.x), "r"(a.y), "r"(a.z), "r"(a.w), "r"(b.x), "r"(b.y));
}

// ---------------------------------------------------------------------------
// P1: normalize memory rows -> frag-major tile images.
// T1F (GEMM1 B fp16, k=channel, *INV_TEMP): [4nt][16ks][32lane] uint2 (16KB)
// T2F (GEMM2 B bf16, k=slot):               [32nt][2ks][32lane]  uint2 (16KB)
// ---------------------------------------------------------------------------
__global__ void pack_mem_kernel(const float* __restrict__ fg, const float* __restrict__ bg){
    __shared__ float rows[KT][CC+4];
    int blk = blockIdx.x;                 // 0..127
    int bank = blk >> 6, tin = blk & 63;
    const float* src = bank ? bg : fg;
    int tid = threadIdx.x, wid = tid>>5, lane = tid&31;

    #pragma unroll
    for (int i = 0; i < 4; i++){
        int r = wid*4 + i;
        int slot = tin*KT + r;
        float4 v0 = make_float4(0.f,0.f,0.f,0.f), v1 = v0;
        if (slot < MM){
            const float4* s4 = (const float4*)(src + (size_t)slot*CC);
            v0 = s4[lane]; v1 = s4[lane+32];
            float ss = v0.x*v0.x+v0.y*v0.y+v0.z*v0.z+v0.w*v0.w
                     + v1.x*v1.x+v1.y*v1.y+v1.z*v1.z+v1.w*v1.w;
            #pragma unroll
            for (int o = 16; o; o >>= 1) ss += __shfl_xor_sync(0xffffffffu, ss, o);
            float inv = 1.0f / fmaxf(sqrtf(ss), 1e-12f);
            v0.x*=inv; v0.y*=inv; v0.z*=inv; v0.w*=inv;
            v1.x*=inv; v1.y*=inv; v1.z*=inv; v1.w*=inv;
        }
        float4* d = (float4*)&rows[r][0];
        d[lane] = v0; d[lane+32] = v1;
    }
    __syncthreads();

    uint2* out = g_timg + (size_t)blk * 4096;
    for (int idx = tid; idx < 2048; idx += 256){
        int nt = idx>>9, ks = (idx>>5)&15, l = idx&31;
        int g = l>>2, t = l&3;
        int slot = nt*8 + g, c = ks*16 + 2*t;
        uint2 v;
        v.x = ph2(rows[slot][c]   * INV_TEMP, rows[slot][c+1] * INV_TEMP);
        v.y = ph2(rows[slot][c+8] * INV_TEMP, rows[slot][c+9] * INV_TEMP);
        out[idx] = v;
    }
    for (int idx = tid; idx < 2048; idx += 256){
        int nt2 = idx>>6, ks2 = (idx>>5)&1, l = idx&31;
        int g = l>>2, t = l&3;
        int ch = nt2*8 + g, s0 = ks2*16 + 2*t;
        uint2 v;
        v.x = pbf2(rows[s0][ch],   rows[s0+1][ch]);
        v.y = pbf2(rows[s0+8][ch], rows[s0+9][ch]);
        out[2048 + idx] = v;
    }
}

// ---------------------------------------------------------------------------
// P2: pack w1 (fg,bg) fp16 B-frags: [bank][8nt][16ks][32lane] uint2
// ---------------------------------------------------------------------------
__global__ void wpack_kernel(const float* __restrict__ w1f, const float* __restrict__ w1b){
    int idx = blockIdx.x*256 + threadIdx.x;      // 0..8191
    int bank = idx >> 12, r = idx & 4095;
    int nt = r>>9, ks = (r>>5)&15, l = r&31;
    int g = l>>2, t = l&3;
    int hcol = nt*8 + g, c = ks*16 + 2*t;
    const float* w = bank ? w1b : w1f;
    uint2 v;
    v.x = ph2(w[c*CHID + hcol],     w[(c+1)*CHID + hcol]);
    v.y = ph2(w[(c+8)*CHID + hcol], w[(c+9)*CHID + hcol]);
    g_wf[idx] = v;
}

// ---------------------------------------------------------------------------
// P3: feats -> g_xn (fp32) + g_qf (fp16 A-frags). One block per 64 pixels.
// ---------------------------------------------------------------------------
__global__ void xn_kernel(const float* __restrict__ feats){
    extern __shared__ float xr[];               // [64][260]
    __shared__ float part[4][64];
    __shared__ float sinv[64];
    int bh = blockIdx.x, b = bh >> 6, h = bh & 63;
    int tid = threadIdx.x;
    int w = tid & 63, cg = tid >> 6;
    float ps = 0.f;
    for (int c = cg; c < CC; c += 4){
        float v = feats[(((size_t)b*CC + c)*64 + h)*64 + w];
        ps = fmaf(v, v, ps);
    }
    part[cg][w] = ps;
    __syncthreads();
    if (tid < 64){
        float s = part[0][tid] + part[1][tid] + part[2][tid] + part[3][tid];
        sinv[tid] = 1.0f / fmaxf(sqrtf(s), 1e-12f);
    }
    __syncthreads();
    int nbase = bh * 64;
    for (int i = tid; i < CC*64; i += 256){
        int ww = i >> 8, c = i & 255;
        float v = feats[(((size_t)b*CC + c)*64 + h)*64 + ww] * sinv[ww];
        g_xn[(size_t)(nbase + ww)*CC + c] = v;
        xr[ww*260 + c] = v;
    }
    __syncthreads();
    uint4* out = g_qf + (size_t)bh * 2048;
    for (int idx = tid; idx < 2048; idx += 256){
        int mt = idx>>9, ks = (idx>>5)&15, l = idx&31;
        int g = l>>2, t = l&3;
        int m = mt*16 + g, k = ks*16 + 2*t;
        uint4 v;
        v.x = ph2(xr[m*260 + k],       xr[m*260 + k+1]);
        v.y = ph2(xr[(m+8)*260 + k],   xr[(m+8)*260 + k+1]);
        v.z = ph2(xr[m*260 + k+8],     xr[m*260 + k+9]);
        v.w = ph2(xr[(m+8)*260 + k+8], xr[(m+8)*260 + k+9]);
        out[idx] = v;
    }
}

// ---------------------------------------------------------------------------
// P4: gate MLPs via fp16 mma. CTA = 64 px; warp: mt=w&3, bank=w>>2.
// ---------------------------------------------------------------------------
__global__ __launch_bounds__(256) void gate_kernel(
    const float* __restrict__ b1f, const float* __restrict__ w2f, const float* __restrict__ b2f,
    const float* __restrict__ b1b, const float* __restrict__ w2b, const float* __restrict__ b2b){
    int cta = blockIdx.x, tid = threadIdx.x, wid = tid>>5, lane = tid&31;
    int mt = wid & 3, bank = wid >> 2;
    const uint4* A = g_qf + (size_t)cta*2048 + mt*512 + lane;
    const uint2* B = g_wf + bank*4096 + lane;

    float acc[8][4];
    #pragma unroll
    for (int nt = 0; nt < 8; nt++)
        acc[nt][0] = acc[nt][1] = acc[nt][2] = acc[nt][3] = 0.f;

    #pragma unroll 4
    for (int ks = 0; ks < 16; ks++){
        uint4 a = A[ks*32];
        #pragma unroll
        for (int nt = 0; nt < 8; nt++)
            mma16(acc[nt], a, B[(nt*16 + ks)*32]);
    }

    const float* b1 = bank ? b1b : b1f;
    const float* w2 = bank ? w2b : w2f;
    float bias2 = bank ? b2b[0] : b2f[0];
    float sA = 0.f, sB = 0.f;
    #pragma unroll
    for (int nt = 0; nt < 8; nt++){
        #pragma unroll
        for (int c = 0; c < 4; c++){
            int col = nt*8 + 2*(lane&3) + (c&1);
            float hv = fmaxf(acc[nt][c] + b1[col], 0.f) * w2[col];
            if (c < 2) sA += hv; else sB += hv;
        }
    }
    sA += __shfl_xor_sync(0xffffffffu, sA, 1);
    sA += __shfl_xor_sync(0xffffffffu, sA, 2);
    sB += __shfl_xor_sync(0xffffffffu, sB, 1);
    sB += __shfl_xor_sync(0xffffffffu, sB, 2);
    if ((lane & 3) == 0){
        int rA = cta*64 + mt*16 + (lane>>2);
        float* dst = bank ? g_gbg : g_gfg;
        dst[rA]     = 1.0f / (1.0f + __expf(-(sA + bias2)));
        dst[rA + 8] = 1.0f / (1.0f + __expf(-(sB + bias2)));
    }
}

// ---------------------------------------------------------------------------
// P5: fused dual attention. CTA = 64 pixels, 4 warps, occupancy 2.
// GEMM1: 1mt x 4nt x 16ks (fp16); P register-forwarded; GEMM2: 1mt x 32nt x 2ks (bf16).
// NO per-tile __syncthreads: full[2] tx-mbarriers + empty[2] (count=4) mbarriers;
// producer warp (= buf) refills a buffer only after all 4 warps arrived empty.
// ---------------------------------------------------------------------------
__global__ __launch_bounds__(128, 2) void attn_kernel(float* __restrict__ out){
    extern __shared__ __align__(16) char sm[];
    __shared__ __align__(8) unsigned long long barsm[5];   // qbar, full[2], empty[2]

    const int tid = threadIdx.x, wid = tid >> 5, lane = tid & 31;
    const int g = lane >> 2, t = lane & 3;
    const int cta = blockIdx.x;

    const uint32_t smb = s2u(sm);
    const uint4* QF4 = (const uint4*)(sm + QF_OFF);
    const uint32_t qbar = s2u(barsm);
    const uint32_t full0 = qbar + 8,  full1 = qbar + 16;
    const uint32_t emp0  = qbar + 24, emp1  = qbar + 32;

    if (tid == 0){
        mbar_init(qbar, 1);
        mbar_init(full0, 1); mbar_init(full1, 1);
        mbar_init(emp0, 4);  mbar_init(emp1, 4);
    }
    __syncthreads();
    if (tid == 0){
        mbar_tx(qbar, 32768);
        bulk_g2s(smb + QF_OFF, g_qf + (size_t)cta*2048, 32768, qbar);
        mbar_tx(full0, TB_SZ);
        bulk_g2s(smb + TB_OFF, g_timg, TB_SZ, full0);
        mbar_tx(full1, TB_SZ);
        bulk_g2s(smb + TB_OFF + TB_SZ, g_timg + 4096, TB_SZ, full1);
    }
    mbar_wait(qbar, 0);

    const int rA = cta*64 + wid*16 + g;      // this thread's row A
    const int rB = rA + 8;                   // row B

    for (int pass = 0; pass < 2; pass++){
        float accO[32][4];
        #pragma unroll
        for (int j = 0; j < 32; j++)
            accO[j][0] = accO[j][1] = accO[j][2] = accO[j][3] = 0.f;
        float lA = 0.f, lB = 0.f;
        const float gA = pass ? g_gbg[rA] : g_gfg[rA];
        const float gB = pass ? g_gbg[rB] : g_gfg[rB];

        for (int tt = 0; tt < NTILE; tt++){
            const int tgl = pass*NTILE + tt;
            const int buf = tgl & 1;
            char* TB = sm + TB_OFF + buf*TB_SZ;
            const uint32_t fullb = buf ? full1 : full0;
            const uint32_t empb  = buf ? emp1  : emp0;
            const uint32_t use   = (uint32_t)(tgl >> 1);   // usage index of this buffer

            mbar_wait(fullb, use & 1);

            // ---- GEMM1: 1mt x 4nt x 16ks (fp16) ----
            float accS[4][4];
            #pragma unroll
            for (int j = 0; j < 4; j++)
                accS[j][0] = accS[j][1] = accS[j][2] = accS[j][3] = 0.f;
            {
                const uint4* Aq = QF4 + wid*512 + lane;
                const uint2* Bq = (const uint2*)TB + lane;
                #pragma unroll
                for (int ks = 0; ks < 16; ks++){
                    uint4 a = Aq[ks*32];
                    mma16(accS[0], a, Bq[(ks      )*32]);
                    mma16(accS[1], a, Bq[(ks + 16 )*32]);
                    mma16(accS[2], a, Bq[(ks + 32 )*32]);
                    mma16(accS[3], a, Bq[(ks + 48 )*32]);
                }
            }

            // ---- exp + pack P into GEMM2 A-frags (registers); fp32 lsum ----
            uint4 aP[2];
            {
                const bool last = (tt == NTILE-1);
                #pragma unroll
                for (int ks2 = 0; ks2 < 2; ks2++){
                    #pragma unroll
                    for (int h = 0; h < 2; h++){
                        const int nt = 2*ks2 + h;
                        float p0 = __expf(accS[nt][0]);
                        float p1 = __expf(accS[nt][1]);
                        float p2 = __expf(accS[nt][2]);
                        float p3 = __expf(accS[nt][3]);
                        if (last && nt > 0){ p0 = p1 = p2 = p3 = 0.f; }
                        lA += p0 + p1;
                        lB += p2 + p3;
                        uint32_t uA = pbf2(p0, p1);
                        uint32_t uB = pbf2(p2, p3);
                        if (h == 0){ aP[ks2].x = uA; aP[ks2].y = uB; }
                        else        { aP[ks2].z = uA; aP[ks2].w = uB; }
                    }
                }
            }

            // ---- GEMM2: 1mt x 32nt x 2ks (bf16), A in registers ----
            {
                const uint2* B2 = (const uint2*)(TB + 16384) + lane;
                #pragma unroll
                for (int ks2 = 0; ks2 < 2; ks2++){
                    uint4 a = aP[ks2];
                    #pragma unroll
                    for (int j = 0; j < 32; j++)
                        mma16b(accO[j], a, B2[(j*2 + ks2)*32]);
                }
            }

            // ---- done reading this buffer ----
            __syncwarp();
            if (lane == 0) mbar_arrive(empb);

            // ---- producer: warp 'buf' refills this buffer with tile tgl+2 ----
            if (wid == buf && tgl + 2 < NTT){
                if (lane == 0){
                    mbar_wait(empb, use & 1);          // all 4 warps done with usage 'use'
                    mbar_tx(fullb, TB_SZ);
                    bulk_g2s(smb + TB_OFF + buf*TB_SZ, g_timg + (size_t)(tgl+2)*4096, TB_SZ, fullb);
                }
                __syncwarp();
            }
        }

        // ---- row sums: quad-reduce over t ----
        lA += __shfl_xor_sync(0xffffffffu, lA, 1);
        lA += __shfl_xor_sync(0xffffffffu, lA, 2);
        lB += __shfl_xor_sync(0xffffffffu, lB, 1);
        lB += __shfl_xor_sync(0xffffffffu, lB, 2);

        // ---- output epilogue (per-warp independent) ----
        {
            const float cA = gA / lA;
            const float cB = gB / lB;
            const size_t baseA = ((size_t)(rA >> 12) * CC) * 4096 + (rA & 4095);
            const size_t baseB = baseA + 8;
            const float* xnA = g_xn + (size_t)rA*CC;
            const float* xnB = g_xn + (size_t)rB*CC;
            #pragma unroll
            for (int j = 0; j < 32; j++){
                int c0 = j*8 + 2*t;
                size_t aA = baseA + (size_t)c0*4096;
                size_t aB = baseB + (size_t)c0*4096;
                if (pass == 0){
                    out[aA]        = xnA[c0]   + cA*accO[j][0];
                    out[aA + 4096] = xnA[c0+1] + cA*accO[j][1];
                    out[aB]        = xnB[c0]   + cB*accO[j][2];
                    out[aB + 4096] = xnB[c0+1] + cB*accO[j][3];
                } else {
                    out[aA]        -= cA*accO[j][0];
                    out[aA + 4096] -= cA*accO[j][1];
                    out[aB]        -= cB*accO[j][2];
                    out[aB + 4096] -= cB*accO[j][3];
                }
            }
        }
    }
}

// ---------------------------------------------------------------------------
extern "C" void kernel_launch(void* const* d_in, const int* in_sizes, int n_in,
                              void* d_out, int out_size){
    const float* feats = (const float*)d_in[0];
    const float* fgm   = (const float*)d_in[1];
    const float* bgm   = (const float*)d_in[2];
    const float* w1f   = (const float*)d_in[3];
    const float* b1f   = (const float*)d_in[4];
    const float* w2f   = (const float*)d_in[5];
    const float* b2f   = (const float*)d_in[6];
    const float* w1b   = (const float*)d_in[7];
    const float* b1b   = (const float*)d_in[8];
    const float* w2b   = (const float*)d_in[9];
    const float* b2b   = (const float*)d_in[10];
    float* out = (float*)d_out;

    cudaFuncSetAttribute(attn_kernel, cudaFuncAttributeMaxDynamicSharedMemorySize, SMEM_DYN);
    cudaFuncSetAttribute(xn_kernel, cudaFuncAttributeMaxDynamicSharedMemorySize, XN_SMEM);

    pack_mem_kernel<<<128, 256>>>(fgm, bgm);
    wpack_kernel<<<32, 256>>>(w1f, w1b);
    xn_kernel<<<512, 256, XN_SMEM>>>(feats);
    gate_kernel<<<512, 256>>>(b1f, w2f, b2f, b1b, w2b, b2b);
    attn_kernel<<<NPIX / PT, 128, SMEM_DYN>>>(out);
}

// round 16
// speedup vs baseline: 1.2945x; 1.0122x over previous
#include <cuda_runtime.h>
#include <cuda_fp16.h>
#include <cuda_bf16.h>
#include <cstdint>

#define CC   256
#define MM   2024
#define NPIX 32768
#define CHID 64
#define PT   64
#define KT   32
#define NTILE 64          // tiles per bank
#define NTT  128          // total (fg+bg)
#define INV_TEMP (1.0f/0.03f)

// attn dynamic smem: 2 tile buffers (T1F fp16 16KB + T2F bf16 16KB each)
#define TB_OFF   0
#define TB_SZ    32768
#define SMEM_DYN 65536

#define XN_SMEM (64*260*4)

// ---------------- global scratch ----------------
__device__ float g_xn[(size_t)NPIX*CC];
__device__ float g_gfg[NPIX];
__device__ float g_gbg[NPIX];
__device__ __align__(16) uint4 g_qf[(size_t)(NPIX/64)*2048];   // fp16 A-frags, [64px blocks][4mt][16ks][32lane]
__device__ __align__(16) uint2 g_timg[(size_t)NTT*4096];       // 128 tiles * 32KB
__device__ __align__(16) uint2 g_wf[8192];                     // w1 fp16 B-frags (fg+bg)

// ---------------- helpers ----------------
__device__ __forceinline__ uint32_t s2u(const void* p){
    uint32_t a;
    asm("{ .reg .u64 t; cvta.to.shared.u64 t, %1; cvt.u32.u64 %0, t; }" : "=r"(a) : "l"(p));
    return a;
}
__device__ __forceinline__ uint32_t ph2(float x, float y){
    __half2 h = __floats2half2_rn(x, y);
    return *(uint32_t*)&h;
}
__device__ __forceinline__ uint32_t pbf2(float x, float y){
    __nv_bfloat162 h = __floats2bfloat162_rn(x, y);
    return *(uint32_t*)&h;
}
__device__ __forceinline__ void mbar_init(uint32_t m, uint32_t c){
    asm volatile("mbarrier.init.shared.b64 [%0], %1;" :: "r"(m), "r"(c) : "memory");
}
__device__ __forceinline__ void mbar_tx(uint32_t m, uint32_t b){
    asm volatile("mbarrier.arrive.expect_tx.shared.b64 _, [%0], %1;" :: "r"(m), "r"(b) : "memory");
}
__device__ __forceinline__ void mbar_arrive(uint32_t m){
    asm volatile("mbarrier.arrive.shared.b64 _, [%0];" :: "r"(m) : "memory");
}
__device__ __forceinline__ void mbar_wait(uint32_t m, uint32_t ph){
    asm volatile(
        "{\n\t.reg .pred P;\n\t"
        "W_%=:\n\t"
        "mbarrier.try_wait.parity.acquire.cta.shared::cta.b64 P, [%0], %1, 0x989680;\n\t"
        "@P bra D_%=;\n\tbra W_%=;\n\tD_%=:\n\t}"
        :: "r"(m), "r"(ph) : "memory");
}
__device__ __forceinline__ void bulk_g2s(uint32_t dst, const void* src, uint32_t bytes, uint32_t mbar){
    asm volatile("cp.async.bulk.shared::cluster.global.mbarrier::complete_tx::bytes [%0], [%1], %2, [%3];"
        :: "r"(dst), "l"(src), "r"(bytes), "r"(mbar) : "memory");
}
// m16n8k16 fp16 mma, fp32 accum
__device__ __forceinline__ void mma16(float* d, uint4 a, uint2 b){
    asm volatile("mma.sync.aligned.m16n8k16.row.col.f32.f16.f16.f32 "
        "{%0,%1,%2,%3}, {%4,%5,%6,%7}, {%8,%9}, {%0,%1,%2,%3};"
        : "+f"(d[0]), "+f"(d[1]), "+f"(d[2]), "+f"(d[3])
        : "r"(a.x), "r"(a.y), "r"(a.z), "r"(a.w), "r"(b.x), "r"(b.y));
}
// m16n8k16 bf16 mma, fp32 accum
__device__ __forceinline__ void mma16b(float* d, uint4 a, uint2 b){
    asm volatile("mma.sync.aligned.m16n8k16.row.col.f32.bf16.bf16.f32 "
        "{%0,%1,%2,%3}, {%4,%5,%6,%7}, {%8,%9}, {%0,%1,%2,%3};"
        : "+f"(d[0]), "+f"(d[1]), "+f"(d[2]), "+f"(d[3])
        : "r"(a.x), "r"(a.y), "r"(a.z), "r"(a.w), "r"(b.x), "r"(b.y));
}

// ---------------------------------------------------------------------------
// P1: normalize memory rows -> frag-major tile images.
// T1F (GEMM1 B fp16, k=channel, *INV_TEMP): [4nt][16ks][32lane] uint2 (16KB)
// T2F (GEMM2 B bf16, k=slot):               [32nt][2ks][32lane]  uint2 (16KB)
// ---------------------------------------------------------------------------
__global__ void pack_mem_kernel(const float* __restrict__ fg, const float* __restrict__ bg){
    __shared__ float rows[KT][CC+4];
    int blk = blockIdx.x;                 // 0..127
    int bank = blk >> 6, tin = blk & 63;
    const float* src = bank ? bg : fg;
    int tid = threadIdx.x, wid = tid>>5, lane = tid&31;

    #pragma unroll
    for (int i = 0; i < 4; i++){
        int r = wid*4 + i;
        int slot = tin*KT + r;
        float4 v0 = make_float4(0.f,0.f,0.f,0.f), v1 = v0;
        if (slot < MM){
            const float4* s4 = (const float4*)(src + (size_t)slot*CC);
            v0 = s4[lane]; v1 = s4[lane+32];
            float ss = v0.x*v0.x+v0.y*v0.y+v0.z*v0.z+v0.w*v0.w
                     + v1.x*v1.x+v1.y*v1.y+v1.z*v1.z+v1.w*v1.w;
            #pragma unroll
            for (int o = 16; o; o >>= 1) ss += __shfl_xor_sync(0xffffffffu, ss, o);
            float inv = 1.0f / fmaxf(sqrtf(ss), 1e-12f);
            v0.x*=inv; v0.y*=inv; v0.z*=inv; v0.w*=inv;
            v1.x*=inv; v1.y*=inv; v1.z*=inv; v1.w*=inv;
        }
        float4* d = (float4*)&rows[r][0];
        d[lane] = v0; d[lane+32] = v1;
    }
    __syncthreads();

    uint2* out = g_timg + (size_t)blk * 4096;
    for (int idx = tid; idx < 2048; idx += 256){
        int nt = idx>>9, ks = (idx>>5)&15, l = idx&31;
        int g = l>>2, t = l&3;
        int slot = nt*8 + g, c = ks*16 + 2*t;
        uint2 v;
        v.x = ph2(rows[slot][c]   * INV_TEMP, rows[slot][c+1] * INV_TEMP);
        v.y = ph2(rows[slot][c+8] * INV_TEMP, rows[slot][c+9] * INV_TEMP);
        out[idx] = v;
    }
    for (int idx = tid; idx < 2048; idx += 256){
        int nt2 = idx>>6, ks2 = (idx>>5)&1, l = idx&31;
        int g = l>>2, t = l&3;
        int ch = nt2*8 + g, s0 = ks2*16 + 2*t;
        uint2 v;
        v.x = pbf2(rows[s0][ch],   rows[s0+1][ch]);
        v.y = pbf2(rows[s0+8][ch], rows[s0+9][ch]);
        out[2048 + idx] = v;
    }
}

// ---------------------------------------------------------------------------
// P2: pack w1 (fg,bg) fp16 B-frags: [bank][8nt][16ks][32lane] uint2
// ---------------------------------------------------------------------------
__global__ void wpack_kernel(const float* __restrict__ w1f, const float* __restrict__ w1b){
    int idx = blockIdx.x*256 + threadIdx.x;      // 0..8191
    int bank = idx >> 12, r = idx & 4095;
    int nt = r>>9, ks = (r>>5)&15, l = r&31;
    int g = l>>2, t = l&3;
    int hcol = nt*8 + g, c = ks*16 + 2*t;
    const float* w = bank ? w1b : w1f;
    uint2 v;
    v.x = ph2(w[c*CHID + hcol],     w[(c+1)*CHID + hcol]);
    v.y = ph2(w[(c+8)*CHID + hcol], w[(c+9)*CHID + hcol]);
    g_wf[idx] = v;
}

// ---------------------------------------------------------------------------
// P3: feats -> g_xn (fp32) + g_qf (fp16 A-frags). One block per 64 pixels.
// ---------------------------------------------------------------------------
__global__ void xn_kernel(const float* __restrict__ feats){
    extern __shared__ float xr[];               // [64][260]
    __shared__ float part[4][64];
    __shared__ float sinv[64];
    int bh = blockIdx.x, b = bh >> 6, h = bh & 63;
    int tid = threadIdx.x;
    int w = tid & 63, cg = tid >> 6;
    float ps = 0.f;
    for (int c = cg; c < CC; c += 4){
        float v = feats[(((size_t)b*CC + c)*64 + h)*64 + w];
        ps = fmaf(v, v, ps);
    }
    part[cg][w] = ps;
    __syncthreads();
    if (tid < 64){
        float s = part[0][tid] + part[1][tid] + part[2][tid] + part[3][tid];
        sinv[tid] = 1.0f / fmaxf(sqrtf(s), 1e-12f);
    }
    __syncthreads();
    int nbase = bh * 64;
    for (int i = tid; i < CC*64; i += 256){
        int ww = i >> 8, c = i & 255;
        float v = feats[(((size_t)b*CC + c)*64 + h)*64 + ww] * sinv[ww];
        g_xn[(size_t)(nbase + ww)*CC + c] = v;
        xr[ww*260 + c] = v;
    }
    __syncthreads();
    uint4* out = g_qf + (size_t)bh * 2048;
    for (int idx = tid; idx < 2048; idx += 256){
        int mt = idx>>9, ks = (idx>>5)&15, l = idx&31;
        int g = l>>2, t = l&3;
        int m = mt*16 + g, k = ks*16 + 2*t;
        uint4 v;
        v.x = ph2(xr[m*260 + k],       xr[m*260 + k+1]);
        v.y = ph2(xr[(m+8)*260 + k],   xr[(m+8)*260 + k+1]);
        v.z = ph2(xr[m*260 + k+8],     xr[m*260 + k+9]);
        v.w = ph2(xr[(m+8)*260 + k+8], xr[(m+8)*260 + k+9]);
        out[idx] = v;
    }
}

// ---------------------------------------------------------------------------
// P4: gate MLPs via fp16 mma. CTA = 64 px; warp: mt=w&3, bank=w>>2.
// ---------------------------------------------------------------------------
__global__ __launch_bounds__(256) void gate_kernel(
    const float* __restrict__ b1f, const float* __restrict__ w2f, const float* __restrict__ b2f,
    const float* __restrict__ b1b, const float* __restrict__ w2b, const float* __restrict__ b2b){
    int cta = blockIdx.x, tid = threadIdx.x, wid = tid>>5, lane = tid&31;
    int mt = wid & 3, bank = wid >> 2;
    const uint4* A = g_qf + (size_t)cta*2048 + mt*512 + lane;
    const uint2* B = g_wf + bank*4096 + lane;

    float acc[8][4];
    #pragma unroll
    for (int nt = 0; nt < 8; nt++)
        acc[nt][0] = acc[nt][1] = acc[nt][2] = acc[nt][3] = 0.f;

    #pragma unroll 4
    for (int ks = 0; ks < 16; ks++){
        uint4 a = A[ks*32];
        #pragma unroll
        for (int nt = 0; nt < 8; nt++)
            mma16(acc[nt], a, B[(nt*16 + ks)*32]);
    }

    const float* b1 = bank ? b1b : b1f;
    const float* w2 = bank ? w2b : w2f;
    float bias2 = bank ? b2b[0] : b2f[0];
    float sA = 0.f, sB = 0.f;
    #pragma unroll
    for (int nt = 0; nt < 8; nt++){
        #pragma unroll
        for (int c = 0; c < 4; c++){
            int col = nt*8 + 2*(lane&3) + (c&1);
            float hv = fmaxf(acc[nt][c] + b1[col], 0.f) * w2[col];
            if (c < 2) sA += hv; else sB += hv;
        }
    }
    sA += __shfl_xor_sync(0xffffffffu, sA, 1);
    sA += __shfl_xor_sync(0xffffffffu, sA, 2);
    sB += __shfl_xor_sync(0xffffffffu, sB, 1);
    sB += __shfl_xor_sync(0xffffffffu, sB, 2);
    if ((lane & 3) == 0){
        int rA = cta*64 + mt*16 + (lane>>2);
        float* dst = bank ? g_gbg : g_gfg;
        dst[rA]     = 1.0f / (1.0f + __expf(-(sA + bias2)));
        dst[rA + 8] = 1.0f / (1.0f + __expf(-(sB + bias2)));
    }
}

// ---------------------------------------------------------------------------
// P5: fused dual attention. CTA = 64 pixels, 4 warps, occupancy 2.
// Q A-frags in REGISTERS (loaded once via LDG; loop-invariant).
// GEMM1: 1mt x 4nt x 16ks (fp16); P register-forwarded; GEMM2: 1mt x 32nt x 2ks (bf16).
// full[2] tx-mbarriers + empty[2] (count=4); producer warp (= buf) refills.
// ---------------------------------------------------------------------------
__global__ __launch_bounds__(128, 2) void attn_kernel(float* __restrict__ out){
    extern __shared__ __align__(16) char sm[];
    __shared__ __align__(8) unsigned long long barsm[4];   // full[2], empty[2]

    const int tid = threadIdx.x, wid = tid >> 5, lane = tid & 31;
    const int g = lane >> 2, t = lane & 3;
    const int cta = blockIdx.x;

    const uint32_t smb = s2u(sm);
    const uint32_t bb = s2u(barsm);
    const uint32_t full0 = bb,      full1 = bb + 8;
    const uint32_t emp0  = bb + 16, emp1  = bb + 24;

    if (tid == 0){
        mbar_init(full0, 1); mbar_init(full1, 1);
        mbar_init(emp0, 4);  mbar_init(emp1, 4);
    }
    __syncthreads();
    if (tid == 0){
        mbar_tx(full0, TB_SZ);
        bulk_g2s(smb + TB_OFF, g_timg, TB_SZ, full0);
        mbar_tx(full1, TB_SZ);
        bulk_g2s(smb + TB_OFF + TB_SZ, g_timg + 4096, TB_SZ, full1);
    }

    // ---- Q A-frags into registers (16 uint4, once; overlaps with first bulk) ----
    uint4 Qreg[16];
    {
        const uint4* Ag = g_qf + (size_t)cta*2048 + wid*512 + lane;
        #pragma unroll
        for (int ks = 0; ks < 16; ks++) Qreg[ks] = Ag[ks*32];
    }

    const int rA = cta*64 + wid*16 + g;      // this thread's row A
    const int rB = rA + 8;                   // row B

    for (int pass = 0; pass < 2; pass++){
        float accO[32][4];
        #pragma unroll
        for (int j = 0; j < 32; j++)
            accO[j][0] = accO[j][1] = accO[j][2] = accO[j][3] = 0.f;
        float lA = 0.f, lB = 0.f;
        const float gA = pass ? g_gbg[rA] : g_gfg[rA];
        const float gB = pass ? g_gbg[rB] : g_gfg[rB];

        for (int tt = 0; tt < NTILE; tt++){
            const int tgl = pass*NTILE + tt;
            const int buf = tgl & 1;
            char* TB = sm + TB_OFF + buf*TB_SZ;
            const uint32_t fullb = buf ? full1 : full0;
            const uint32_t empb  = buf ? emp1  : emp0;
            const uint32_t use   = (uint32_t)(tgl >> 1);   // usage index of this buffer

            mbar_wait(fullb, use & 1);

            // ---- GEMM1: 1mt x 4nt x 16ks (fp16), A in registers ----
            float accS[4][4];
            #pragma unroll
            for (int j = 0; j < 4; j++)
                accS[j][0] = accS[j][1] = accS[j][2] = accS[j][3] = 0.f;
            {
                const uint2* Bq = (const uint2*)TB + lane;
                #pragma unroll
                for (int ks = 0; ks < 16; ks++){
                    uint4 a = Qreg[ks];
                    mma16(accS[0], a, Bq[(ks      )*32]);
                    mma16(accS[1], a, Bq[(ks + 16 )*32]);
                    mma16(accS[2], a, Bq[(ks + 32 )*32]);
                    mma16(accS[3], a, Bq[(ks + 48 )*32]);
                }
            }

            // ---- exp + pack P into GEMM2 A-frags (registers); fp32 lsum ----
            uint4 aP[2];
            {
                const bool last = (tt == NTILE-1);
                #pragma unroll
                for (int ks2 = 0; ks2 < 2; ks2++){
                    #pragma unroll
                    for (int h = 0; h < 2; h++){
                        const int nt = 2*ks2 + h;
                        float p0 = __expf(accS[nt][0]);
                        float p1 = __expf(accS[nt][1]);
                        float p2 = __expf(accS[nt][2]);
                        float p3 = __expf(accS[nt][3]);
                        if (last && nt > 0){ p0 = p1 = p2 = p3 = 0.f; }
                        lA += p0 + p1;
                        lB += p2 + p3;
                        uint32_t uA = pbf2(p0, p1);
                        uint32_t uB = pbf2(p2, p3);
                        if (h == 0){ aP[ks2].x = uA; aP[ks2].y = uB; }
                        else        { aP[ks2].z = uA; aP[ks2].w = uB; }
                    }
                }
            }

            // ---- GEMM2: 1mt x 32nt x 2ks (bf16), A in registers ----
            {
                const uint2* B2 = (const uint2*)(TB + 16384) + lane;
                #pragma unroll
                for (int ks2 = 0; ks2 < 2; ks2++){
                    uint4 a = aP[ks2];
                    #pragma unroll
                    for (int j = 0; j < 32; j++)
                        mma16b(accO[j], a, B2[(j*2 + ks2)*32]);
                }
            }

            // ---- done reading this buffer ----
            __syncwarp();
            if (lane == 0) mbar_arrive(empb);

            // ---- producer: warp 'buf' refills this buffer with tile tgl+2 ----
            if (wid == buf && tgl + 2 < NTT){
                if (lane == 0){
                    mbar_wait(empb, use & 1);          // all 4 warps done with usage 'use'
                    mbar_tx(fullb, TB_SZ);
                    bulk_g2s(smb + TB_OFF + buf*TB_SZ, g_timg + (size_t)(tgl+2)*4096, TB_SZ, fullb);
                }
                __syncwarp();
            }
        }

        // ---- row sums: quad-reduce over t ----
        lA += __shfl_xor_sync(0xffffffffu, lA, 1);
        lA += __shfl_xor_sync(0xffffffffu, lA, 2);
        lB += __shfl_xor_sync(0xffffffffu, lB, 1);
        lB += __shfl_xor_sync(0xffffffffu, lB, 2);

        // ---- output epilogue (per-warp independent) ----
        {
            const float cA = gA / lA;
            const float cB = gB / lB;
            const size_t baseA = ((size_t)(rA >> 12) * CC) * 4096 + (rA & 4095);
            const size_t baseB = baseA + 8;
            const float* xnA = g_xn + (size_t)rA*CC;
            const float* xnB = g_xn + (size_t)rB*CC;
            #pragma unroll
            for (int j = 0; j < 32; j++){
                int c0 = j*8 + 2*t;
                size_t aA = baseA + (size_t)c0*4096;
                size_t aB = baseB + (size_t)c0*4096;
                if (pass == 0){
                    out[aA]        = xnA[c0]   + cA*accO[j][0];
                    out[aA + 4096] = xnA[c0+1] + cA*accO[j][1];
                    out[aB]        = xnB[c0]   + cB*accO[j][2];
                    out[aB + 4096] = xnB[c0+1] + cB*accO[j][3];
                } else {
                    out[aA]        -= cA*accO[j][0];
                    out[aA + 4096] -= cA*accO[j][1];
                    out[aB]        -= cB*accO[j][2];
                    out[aB + 4096] -= cB*accO[j][3];
                }
            }
        }
    }
}

// ---------------------------------------------------------------------------
extern "C" void kernel_launch(void* const* d_in, const int* in_sizes, int n_in,
                              void* d_out, int out_size){
    const float* feats = (const float*)d_in[0];
    const float* fgm   = (const float*)d_in[1];
    const float* bgm   = (const float*)d_in[2];
    const float* w1f   = (const float*)d_in[3];
    const float* b1f   = (const float*)d_in[4];
    const float* w2f   = (const float*)d_in[5];
    const float* b2f   = (const float*)d_in[6];
    const float* w1b   = (const float*)d_in[7];
    const float* b1b   = (const float*)d_in[8];
    const float* w2b   = (const float*)d_in[9];
    const float* b2b   = (const float*)d_in[10];
    float* out = (float*)d_out;

    cudaFuncSetAttribute(attn_kernel, cudaFuncAttributeMaxDynamicSharedMemorySize, SMEM_DYN);
    cudaFuncSetAttribute(xn_kernel, cudaFuncAttributeMaxDynamicSharedMemorySize, XN_SMEM);

    pack_mem_kernel<<<128, 256>>>(fgm, bgm);
    wpack_kernel<<<32, 256>>>(w1f, w1b);
    xn_kernel<<<512, 256, XN_SMEM>>>(feats);
    gate_kernel<<<512, 256>>>(b1f, w2f, b2f, b1b, w2b, b2b);
    attn_kernel<<<NPIX / PT, 128, SMEM_DYN>>>(out);
}